// round 16
// baseline (speedup 1.0000x reference)
#include <cuda_runtime.h>
#include <cuda_fp16.h>
#include <math.h>
#include <stdint.h>

// Problem constants  (L,G,H,R,S,A,B = 4,8,2048,128,512,64,4096)
#define BB 4096
#define SS 512
#define HH 2048
#define RR 128
#define AA 64
#define GG 8
#define LL 4

// ---------------------------------------------------------------------------
// Scratch (device globals)
// ---------------------------------------------------------------------------
__device__ __align__(16) __half g_x[(size_t)BB * HH];     // activations (fp16)
__device__ __align__(16) float  g_y[(size_t)BB * HH];     // main branch (fp32)
__device__ __align__(16) __half g_h1[(size_t)BB * RR];    // low-rank mid (fp16)
__device__ __align__(16) float  g_h1p[4][(size_t)BB * RR];
__device__ __align__(16) float  g_outp[8][(size_t)BB * AA];
__device__ __align__(16) __half g_Wmt[(size_t)LL * HH * HH];       // W_main^T
__device__ __align__(16) __half g_Wg1t[(size_t)LL * GG * HH * RR]; // W_g1^T
__device__ __align__(16) __half g_Wg2t[(size_t)LL * GG * RR * HH]; // W_g2^T
__device__ __align__(16) __half g_Wint[(size_t)SS * HH];           // W_in^T
__device__ __align__(16) __half g_Wot[(size_t)AA * HH];            // W_out^T
__device__ __align__(16) __half g_sr[(size_t)BB * SS];             // s fp16
__device__ int g_cnt[GG];
__device__ int g_rows[GG * BB];
__device__ int g_eid[BB];
__device__ const float* g_bg1_ptr;

// ---------------------------------------------------------------------------
// helpers
// ---------------------------------------------------------------------------
__device__ __forceinline__ void mma_f16(float* d, const uint32_t* a,
                                        const uint32_t* b) {
    asm volatile(
        "mma.sync.aligned.m16n8k16.row.col.f32.f16.f16.f32 "
        "{%0,%1,%2,%3}, {%4,%5,%6,%7}, {%8,%9}, {%0,%1,%2,%3};"
        : "+f"(d[0]), "+f"(d[1]), "+f"(d[2]), "+f"(d[3])
        : "r"(a[0]), "r"(a[1]), "r"(a[2]), "r"(a[3]), "r"(b[0]), "r"(b[1]));
}
__device__ __forceinline__ void ldsm4(uint32_t& r0, uint32_t& r1, uint32_t& r2,
                                      uint32_t& r3, uint32_t addr) {
    asm volatile("ldmatrix.sync.aligned.m8n8.x4.shared.b16 {%0,%1,%2,%3}, [%4];"
                 : "=r"(r0), "=r"(r1), "=r"(r2), "=r"(r3) : "r"(addr));
}
__device__ __forceinline__ float elu1(float v) {
    return v > 0.0f ? v : expm1f(v);
}
__device__ __forceinline__ void cp16(uint32_t s, const void* g) {
    asm volatile("cp.async.ca.shared.global [%0], [%1], 16;" :: "r"(s), "l"(g));
}
#define CP_COMMIT() asm volatile("cp.async.commit_group;")
#define CP_WAITG(n) asm volatile("cp.async.wait_group %0;" :: "n"(n))

#define HSTR 40                  // halves per smem row (32 data + 8 pad = 80B)
#define H_TILE (128 * HSTR)      // halves per 128-row tile
#define H_STG  (2 * H_TILE)      // halves per stage (A+B), 20480 B
#define G1_A_H (32 * HSTR)       // halves per 32-row A tile
#define G1_STG_H (G1_A_H + H_TILE)  // 6400 halves = 12800 B
#define OUT_B_H (64 * HSTR)      // 64-row B tile (out GEMM)
#define OUT_STG_H (H_TILE + OUT_B_H)  // 7680 halves = 15360 B

// ---------------------------------------------------------------------------
// Routing (resolves {o, b_g1} size-4096 ambiguity by content)
// ---------------------------------------------------------------------------
__global__ void build_routing(const int* __restrict__ c0,
                              const int* __restrict__ c1)
{
    __shared__ const int* o_ptr;
    __shared__ int stride;
    int tid = threadIdx.x;
    if (tid == 0) {
        const int* cands[2] = {c0, c1};
        int pick = 0; stride = 1;
        for (int c = 0; c < 2; c++) {
            const int* p = cands[c];
            bool ok32 = true, nz32 = false;
            for (int i = 0; i < 256; i++) {
                int v = p[i];
                if (v < 0 || v >= GG) { ok32 = false; break; }
                if (v) nz32 = true;
            }
            if (ok32 && nz32) { pick = c; stride = 1; break; }
            bool ok64 = true, nz64 = false;
            for (int i = 0; i < 256; i++) {
                int lo = p[2 * i], hi = p[2 * i + 1];
                if (hi != 0 || lo < 0 || lo >= GG) { ok64 = false; break; }
                if (lo) nz64 = true;
            }
            if (ok64 && nz64) { pick = c; stride = 2; break; }
        }
        o_ptr = cands[pick];
        g_bg1_ptr = (const float*)cands[1 - pick];
    }
    if (tid < GG) g_cnt[tid] = 0;
    __syncthreads();
    const int* o = o_ptr;
    const int st = stride;
    for (int b = tid; b < BB; b += blockDim.x) {
        int e = o[(size_t)b * st];
        g_eid[b] = e;
        int idx = atomicAdd(&g_cnt[e], 1);
        g_rows[e * BB + idx] = b;
    }
}

// ---------------------------------------------------------------------------
// Prep: transpose + fp16 convert. src [K][N] fp32 (batched) -> dst [N][K] fp16.
// Tile 64(K) x 32(N). K mult of 64, N mult of 32.
// ---------------------------------------------------------------------------
__global__ void transpose_h(const float* __restrict__ src,
                            __half* __restrict__ dst, int K, int N)
{
    __shared__ float t[64][33];
    const size_t mb = (size_t)blockIdx.z * K * N;
    int k0 = blockIdx.y * 64, n0 = blockIdx.x * 32;
    int x = threadIdx.x, y = threadIdx.y;  // 32x8
#pragma unroll
    for (int i = y; i < 64; i += 8)
        t[i][x] = src[mb + (size_t)(k0 + i) * N + n0 + x];
    __syncthreads();
#pragma unroll
    for (int j = y; j < 32; j += 8) {
        __half2 v = __floats2half2_rn(t[2 * x][j], t[2 * x + 1][j]);
        *(__half2*)(dst + mb + (size_t)(n0 + j) * K + k0 + 2 * x) = v;
    }
}

__global__ void round_s(const float* __restrict__ s)
{
    int idx = (blockIdx.x * 256 + threadIdx.x) * 4;
    float4 v = *(const float4*)(s + idx);
    *(__half2*)(g_sr + idx)     = __floats2half2_rn(v.x, v.y);
    *(__half2*)(g_sr + idx + 2) = __floats2half2_rn(v.z, v.w);
}

// ---------------------------------------------------------------------------
// Dense fp16 GEMM (m16n8k16), col-pair: each CTA computes TWO adjacent
// 128-col tiles with one continuous 4-slot cp.async ring (no mid drain).
// CTA rows=128, 256 threads = 8 warps each 64x32.  BK=32.  N mult of 256,
// K mult of 128.  Cf!=0 -> fp32 out; else Ch (fp16 out).
// ---------------------------------------------------------------------------
__global__ __launch_bounds__(256)
void hgemm(const __half* __restrict__ A, int lda,
           const __half* __restrict__ Bt, int ldb,
           const float* __restrict__ bias, float* Cf, __half* Ch,
           int N, int K)
{
    extern __shared__ __half hsm[];
    const int tid = threadIdx.x, lane = tid & 31, wid = tid >> 5;
    const int wm = (wid & 1) * 64, wn = (wid >> 1) * 32;
    const int row0 = blockIdx.y * 128;
    const int colbase = blockIdx.x * 256;
    const int r = lane >> 2, cq = lane & 3;
    const uint32_t sbase = (uint32_t)__cvta_generic_to_shared(hsm);

    const uint32_t aAddr0 = sbase +
        ((wm + (lane & 15)) * HSTR + ((lane >> 4) << 3)) * 2;
    const uint32_t bAddr0 = sbase + H_TILE * 2 +
        ((wn + ((lane >> 4) << 3) + (lane & 7)) * HSTR +
         (((lane >> 3) & 1) << 3)) * 2;

    float acc[4][4][4];
#pragma unroll
    for (int t = 0; t < 4; t++)
#pragma unroll
        for (int u = 0; u < 4; u++)
#pragma unroll
            for (int v = 0; v < 4; v++) acc[t][u][v] = 0.0f;

    const int NT = K >> 5;
    const int TT = 2 * NT;
    // tile tt: ct = tt/NT (col tile), k0 = (tt%NT)*32
    auto load_tile = [&](int slot, int tt) {
        const uint32_t sA = sbase + slot * H_STG * 2;
        const uint32_t sB = sA + H_TILE * 2;
        const int k0 = (tt >= NT ? tt - NT : tt) << 5;
        const int c0 = colbase + (tt >= NT ? 128 : 0);
#pragma unroll
        for (int i = 0; i < 2; i++) {
            int cc = tid + i * 256;
            int m = cc >> 2, c = cc & 3;
            cp16(sA + (m * HSTR + c * 8) * 2,
                 A + (size_t)(row0 + m) * lda + k0 + c * 8);
            cp16(sB + (m * HSTR + c * 8) * 2,
                 Bt + (size_t)(c0 + m) * ldb + k0 + c * 8);
        }
    };

    load_tile(0, 0); CP_COMMIT();
    load_tile(1, 1); CP_COMMIT();
    load_tile(2, 2); CP_COMMIT();

    for (int tt = 0; tt < TT; tt++) {
        CP_WAITG(2);
        __syncthreads();
        if (tt + 3 < TT) load_tile((tt + 3) & 3, tt + 3);
        CP_COMMIT();
        const uint32_t off = (tt & 3) * H_STG * 2;
#pragma unroll
        for (int ks = 0; ks < 2; ks++) {
            const uint32_t kb = ks * 32;   // 16 halves = 32 bytes
            uint32_t af[4][4], bf[4][2];
#pragma unroll
            for (int t = 0; t < 4; t++)
                ldsm4(af[t][0], af[t][1], af[t][2], af[t][3],
                      aAddr0 + off + t * 16 * HSTR * 2 + kb);
#pragma unroll
            for (int j = 0; j < 2; j++)
                ldsm4(bf[2*j][0], bf[2*j][1], bf[2*j+1][0], bf[2*j+1][1],
                      bAddr0 + off + j * 16 * HSTR * 2 + kb);
#pragma unroll
            for (int t = 0; t < 4; t++)
#pragma unroll
                for (int u = 0; u < 4; u++)
                    mma_f16(acc[t][u], af[t], bf[u]);
        }

        if ((tt + 1) % NT == 0) {
            // epilogue for col tile ct = tt/NT
            const int col0 = colbase + (tt >= NT ? 128 : 0);
#pragma unroll
            for (int t = 0; t < 4; t++) {
                int row_a = row0 + wm + t * 16 + r;
#pragma unroll
                for (int u = 0; u < 4; u++) {
                    int col = col0 + wn + u * 8 + cq * 2;
                    float b0 = bias[col], b1 = bias[col + 1];
                    float v00 = acc[t][u][0] + b0, v01 = acc[t][u][1] + b1;
                    float v10 = acc[t][u][2] + b0, v11 = acc[t][u][3] + b1;
                    if (Cf) {
                        *(float2*)(Cf + (size_t)row_a * N + col) = {v00, v01};
                        *(float2*)(Cf + (size_t)(row_a + 8) * N + col) = {v10, v11};
                    } else {
                        *(__half2*)(Ch + (size_t)row_a * N + col) =
                            __floats2half2_rn(v00, v01);
                        *(__half2*)(Ch + (size_t)(row_a + 8) * N + col) =
                            __floats2half2_rn(v10, v11);
                    }
#pragma unroll
                    for (int v = 0; v < 4; v++) acc[t][u][v] = 0.0f;
                }
            }
        }
    }
}

// ---------------------------------------------------------------------------
// g1 split-K partial (fp16, 4-stage, single sync): BM=32, N=RR, K chunk 512.
// 4 splits.  256 threads, 8 warps each 32x16.
// ---------------------------------------------------------------------------
__global__ __launch_bounds__(256)
void hgemm_g1p(int l)
{
    const int g = blockIdx.z;
    const int cnt = g_cnt[g];
    const int mbase = blockIdx.y * 32;
    if (mbase >= cnt) return;
    const int split = blockIdx.x;
    const int kstart = split * (HH / 4);
    const int* rows = g_rows + g * BB;
    const __half* Bt = g_Wg1t + ((size_t)(l * GG + g)) * HH * RR;  // [RR][HH]
    float* outp = g_h1p[split];

    extern __shared__ __half hsm[];
    int* rows_s = (int*)(hsm + 4 * G1_STG_H);
    const uint32_t sbase = (uint32_t)__cvta_generic_to_shared(hsm);

    const int tid = threadIdx.x, lane = tid & 31, wid = tid >> 5;
    const int wn = wid * 16;
    const int r = lane >> 2, cq = lane & 3;

    if (tid < 32) {
        int lr = mbase + tid;
        rows_s[tid] = rows[lr < cnt ? lr : (cnt - 1)];
    }
    __syncthreads();

    const uint32_t aAddr0 = sbase +
        ((lane & 15) * HSTR + ((lane >> 4) << 3)) * 2;
    const uint32_t bAddr0 = sbase + G1_A_H * 2 +
        ((wn + ((lane >> 4) << 3) + (lane & 7)) * HSTR +
         (((lane >> 3) & 1) << 3)) * 2;

    float acc[2][2][4];
#pragma unroll
    for (int t = 0; t < 2; t++)
#pragma unroll
        for (int u = 0; u < 2; u++)
#pragma unroll
            for (int v = 0; v < 4; v++) acc[t][u][v] = 0.0f;

    const int NT = 16;   // 512/32
    auto load_tile = [&](int slot, int k0) {
        const uint32_t sA = sbase + slot * G1_STG_H * 2;
        const uint32_t sB = sA + G1_A_H * 2;
        if (tid < 128) {   // A: 32 rows x 4 chunks
            int m = tid >> 2, c = tid & 3;
            cp16(sA + (m * HSTR + c * 8) * 2,
                 g_x + (size_t)rows_s[m] * HH + k0 + c * 8);
        }
#pragma unroll
        for (int i = 0; i < 2; i++) {  // B: 128 rows x 4 chunks
            int cc = tid + i * 256;
            int m = cc >> 2, c = cc & 3;
            cp16(sB + (m * HSTR + c * 8) * 2,
                 Bt + (size_t)m * HH + k0 + c * 8);
        }
    };

#pragma unroll
    for (int p = 0; p < 3; p++) { load_tile(p, kstart + p * 32); CP_COMMIT(); }

    for (int kt = 0; kt < NT; kt++) {
        CP_WAITG(2);
        __syncthreads();
        if (kt + 3 < NT) load_tile((kt + 3) & 3, kstart + (kt + 3) * 32);
        CP_COMMIT();
        const uint32_t off = (kt & 3) * G1_STG_H * 2;
#pragma unroll
        for (int ks = 0; ks < 2; ks++) {
            const uint32_t kb = ks * 32;
            uint32_t af[2][4], bf[2][2];
#pragma unroll
            for (int t = 0; t < 2; t++)
                ldsm4(af[t][0], af[t][1], af[t][2], af[t][3],
                      aAddr0 + off + t * 16 * HSTR * 2 + kb);
            ldsm4(bf[0][0], bf[0][1], bf[1][0], bf[1][1], bAddr0 + off + kb);
#pragma unroll
            for (int t = 0; t < 2; t++)
#pragma unroll
                for (int u = 0; u < 2; u++)
                    mma_f16(acc[t][u], af[t], bf[u]);
        }
    }

#pragma unroll
    for (int t = 0; t < 2; t++) {
        int lr0 = mbase + t * 16 + r;
#pragma unroll
        for (int u = 0; u < 2; u++) {
            int col = wn + u * 8 + cq * 2;
            if (lr0 < cnt) {
                int row = rows[lr0];
                *(float2*)(outp + (size_t)row * RR + col) =
                    {acc[t][u][0], acc[t][u][1]};
            }
            if (lr0 + 8 < cnt) {
                int row = rows[lr0 + 8];
                *(float2*)(outp + (size_t)row * RR + col) =
                    {acc[t][u][2], acc[t][u][3]};
            }
        }
    }
}

// h1 = fp16(sum of 4 partials + b_g1[l, eid]), vectorized x4
__global__ void reduce_h1(int l)
{
    int idx = (blockIdx.x * 256 + threadIdx.x) * 4;
    int b = idx >> 7, c = idx & 127;
    float4 v0 = *(const float4*)(g_h1p[0] + idx);
    float4 v1 = *(const float4*)(g_h1p[1] + idx);
    float4 v2 = *(const float4*)(g_h1p[2] + idx);
    float4 v3 = *(const float4*)(g_h1p[3] + idx);
    const float* bp = g_bg1_ptr + (l * GG + g_eid[b]) * RR + c;
    float r0 = v0.x + v1.x + v2.x + v3.x + bp[0];
    float r1 = v0.y + v1.y + v2.y + v3.y + bp[1];
    float r2 = v0.z + v1.z + v2.z + v3.z + bp[2];
    float r3 = v0.w + v1.w + v2.w + v3.w + bp[3];
    *(__half2*)(g_h1 + idx)     = __floats2half2_rn(r0, r1);
    *(__half2*)(g_h1 + idx + 2) = __floats2half2_rn(r2, r3);
}

// ---------------------------------------------------------------------------
// g2 + fused ELU (fp16), col-pair: each CTA does TWO 128-col tiles with one
// continuous 4-slot ring (8 K-tiles).  256 threads, 8 warps each 64x32.
// x_next = fp16(elu(y + h1 @ Wg2t[l,g]^T + b_g2[l,g]))
// ---------------------------------------------------------------------------
__global__ __launch_bounds__(256)
void hgemm_g2(const float* __restrict__ bg2, int l)
{
    const int g = blockIdx.z;
    const int cnt = g_cnt[g];
    const int mbase = blockIdx.y * 128;
    if (mbase >= cnt) return;
    const int* rows = g_rows + g * BB;
    const int colbase = blockIdx.x * 256;
    const __half* Bt  = g_Wg2t + ((size_t)(l * GG + g)) * RR * HH;  // [HH][RR]
    const float* bias = bg2 + (size_t)(l * GG + g) * HH;

    extern __shared__ __half hsm[];
    int* rows_s = (int*)(hsm + 4 * H_STG);
    const uint32_t sbase = (uint32_t)__cvta_generic_to_shared(hsm);

    const int tid = threadIdx.x, lane = tid & 31, wid = tid >> 5;
    const int wm = (wid & 1) * 64, wn = (wid >> 1) * 32;
    const int r = lane >> 2, cq = lane & 3;

    if (tid < 128) {
        int lr = mbase + tid;
        rows_s[tid] = rows[lr < cnt ? lr : (cnt - 1)];
    }
    __syncthreads();

    const uint32_t aAddr0 = sbase +
        ((wm + (lane & 15)) * HSTR + ((lane >> 4) << 3)) * 2;
    const uint32_t bAddr0 = sbase + H_TILE * 2 +
        ((wn + ((lane >> 4) << 3) + (lane & 7)) * HSTR +
         (((lane >> 3) & 1) << 3)) * 2;

    float acc[4][4][4];
#pragma unroll
    for (int t = 0; t < 4; t++)
#pragma unroll
        for (int u = 0; u < 4; u++)
#pragma unroll
            for (int v = 0; v < 4; v++) acc[t][u][v] = 0.0f;

    const int NT = RR >> 5;  // 4
    const int TT = 2 * NT;   // 8
    auto load_tile = [&](int slot, int tt) {
        const uint32_t sA = sbase + slot * H_STG * 2;
        const uint32_t sB = sA + H_TILE * 2;
        const int k0 = (tt >= NT ? tt - NT : tt) << 5;
        const int c0 = colbase + (tt >= NT ? 128 : 0);
#pragma unroll
        for (int i = 0; i < 2; i++) {
            int cc = tid + i * 256;
            int m = cc >> 2, c = cc & 3;
            cp16(sA + (m * HSTR + c * 8) * 2,
                 g_h1 + (size_t)rows_s[m] * RR + k0 + c * 8);
            cp16(sB + (m * HSTR + c * 8) * 2,
                 Bt + (size_t)(c0 + m) * RR + k0 + c * 8);
        }
    };

    load_tile(0, 0); CP_COMMIT();
    load_tile(1, 1); CP_COMMIT();
    load_tile(2, 2); CP_COMMIT();

    for (int tt = 0; tt < TT; tt++) {
        CP_WAITG(2);
        __syncthreads();
        if (tt + 3 < TT) load_tile((tt + 3) & 3, tt + 3);
        CP_COMMIT();
        const uint32_t off = (tt & 3) * H_STG * 2;
#pragma unroll
        for (int ks = 0; ks < 2; ks++) {
            const uint32_t kb = ks * 32;
            uint32_t af[4][4], bf[4][2];
#pragma unroll
            for (int t = 0; t < 4; t++)
                ldsm4(af[t][0], af[t][1], af[t][2], af[t][3],
                      aAddr0 + off + t * 16 * HSTR * 2 + kb);
#pragma unroll
            for (int j = 0; j < 2; j++)
                ldsm4(bf[2*j][0], bf[2*j][1], bf[2*j+1][0], bf[2*j+1][1],
                      bAddr0 + off + j * 16 * HSTR * 2 + kb);
#pragma unroll
            for (int t = 0; t < 4; t++)
#pragma unroll
                for (int u = 0; u < 4; u++)
                    mma_f16(acc[t][u], af[t], bf[u]);
        }

        if ((tt + 1) % NT == 0) {
            const int col0 = colbase + (tt >= NT ? 128 : 0);
#pragma unroll
            for (int t = 0; t < 4; t++) {
                int lr0 = mbase + wm + t * 16 + r;
#pragma unroll
                for (int u = 0; u < 4; u++) {
                    int col = col0 + wn + u * 8 + cq * 2;
                    float b0 = bias[col], b1 = bias[col + 1];
                    if (lr0 < cnt) {
                        int row = rows[lr0];
                        const float* yp = g_y + (size_t)row * HH + col;
                        *(__half2*)(g_x + (size_t)row * HH + col) =
                            __floats2half2_rn(elu1(yp[0] + acc[t][u][0] + b0),
                                              elu1(yp[1] + acc[t][u][1] + b1));
                    }
                    if (lr0 + 8 < cnt) {
                        int row = rows[lr0 + 8];
                        const float* yp = g_y + (size_t)row * HH + col;
                        *(__half2*)(g_x + (size_t)row * HH + col) =
                            __floats2half2_rn(elu1(yp[0] + acc[t][u][2] + b0),
                                              elu1(yp[1] + acc[t][u][3] + b1));
                    }
#pragma unroll
                    for (int v = 0; v < 4; v++) acc[t][u][v] = 0.0f;
                }
            }
        }
    }
}

// ---------------------------------------------------------------------------
// Output GEMM (fp16 MMA, split-K 8): partial[M,64] = x[M,kc] @ Wot[64,kc]^T
// BM=128, BN=64, BK=32, K chunk 256 (NT=8).  8 warps each 64x16.  4-stage.
// ---------------------------------------------------------------------------
__global__ __launch_bounds__(256)
void hgemm_out(const __half* __restrict__ A, const __half* __restrict__ Bt)
{
    extern __shared__ __half hsm[];
    const int tid = threadIdx.x, lane = tid & 31, wid = tid >> 5;
    const int wm = (wid & 1) * 64, wn = (wid >> 1) * 16;
    const int row0 = blockIdx.y * 128;
    const int split = blockIdx.z;
    const int kstart = split * 256;
    float* outp = g_outp[split];
    const int r = lane >> 2, cq = lane & 3;
    const uint32_t sbase = (uint32_t)__cvta_generic_to_shared(hsm);

    const uint32_t aAddr0 = sbase +
        ((wm + (lane & 15)) * HSTR + ((lane >> 4) << 3)) * 2;
    const uint32_t bAddr0 = sbase + H_TILE * 2 +
        ((wn + ((lane >> 4) << 3) + (lane & 7)) * HSTR +
         (((lane >> 3) & 1) << 3)) * 2;

    float acc[4][2][4];
#pragma unroll
    for (int t = 0; t < 4; t++)
#pragma unroll
        for (int u = 0; u < 2; u++)
#pragma unroll
            for (int v = 0; v < 4; v++) acc[t][u][v] = 0.0f;

    const int NT = 8;  // 256/32
    auto load_tile = [&](int slot, int k0) {
        const uint32_t sA = sbase + slot * OUT_STG_H * 2;
        const uint32_t sB = sA + H_TILE * 2;
#pragma unroll
        for (int i = 0; i < 2; i++) {   // A: 128 rows x 4 chunks = 512
            int cc = tid + i * 256;
            int m = cc >> 2, c = cc & 3;
            cp16(sA + (m * HSTR + c * 8) * 2,
                 A + (size_t)(row0 + m) * HH + k0 + c * 8);
        }
        {   // B: 64 rows x 4 chunks = 256
            int m = tid >> 2, c = tid & 3;
            if (m < 64)
                cp16(sB + (m * HSTR + c * 8) * 2,
                     Bt + (size_t)m * HH + k0 + c * 8);
        }
    };

#pragma unroll
    for (int p = 0; p < 3; p++) { load_tile(p, kstart + p * 32); CP_COMMIT(); }

    for (int kt = 0; kt < NT; kt++) {
        CP_WAITG(2);
        __syncthreads();
        if (kt + 3 < NT) load_tile((kt + 3) & 3, kstart + (kt + 3) * 32);
        CP_COMMIT();
        const uint32_t off = (kt & 3) * OUT_STG_H * 2;
#pragma unroll
        for (int ks = 0; ks < 2; ks++) {
            const uint32_t kb = ks * 32;
            uint32_t af[4][4], bf[2][2];
#pragma unroll
            for (int t = 0; t < 4; t++)
                ldsm4(af[t][0], af[t][1], af[t][2], af[t][3],
                      aAddr0 + off + t * 16 * HSTR * 2 + kb);
            ldsm4(bf[0][0], bf[0][1], bf[1][0], bf[1][1], bAddr0 + off + kb);
#pragma unroll
            for (int t = 0; t < 4; t++)
#pragma unroll
                for (int u = 0; u < 2; u++)
                    mma_f16(acc[t][u], af[t], bf[u]);
        }
    }

#pragma unroll
    for (int t = 0; t < 4; t++) {
        int row_a = row0 + wm + t * 16 + r;
#pragma unroll
        for (int u = 0; u < 2; u++) {
            int col = wn + u * 8 + cq * 2;
            *(float2*)(outp + (size_t)row_a * AA + col) =
                {acc[t][u][0], acc[t][u][1]};
            *(float2*)(outp + (size_t)(row_a + 8) * AA + col) =
                {acc[t][u][2], acc[t][u][3]};
        }
    }
}

__global__ void reduce_out(const float* __restrict__ bout,
                           float* __restrict__ out)
{
    int idx = blockIdx.x * 256 + threadIdx.x;
    float v = 0.0f;
#pragma unroll
    for (int p = 0; p < 8; p++) v += g_outp[p][idx];
    out[idx] = v + bout[idx & (AA - 1)];
}

// ---------------------------------------------------------------------------
// Launch
// ---------------------------------------------------------------------------
extern "C" void kernel_launch(void* const* d_in, const int* in_sizes, int n_in,
                              void* d_out, int out_size)
{
    const float* s = 0; const float* W_in = 0; const float* b_in = 0;
    const float* W_main = 0; const float* b_main = 0; const float* b_g2 = 0;
    const float* W_out = 0; const float* b_out = 0;
    const float* w8[2] = {0, 0};
    const void*  c4[2] = {0, 0};
    int n8 = 0, n4 = 0;

    for (int i = 0; i < n_in; i++) {
        switch (in_sizes[i]) {
            case 2097152:  s      = (const float*)d_in[i]; break;
            case 1048576:  W_in   = (const float*)d_in[i]; break;
            case 2048:     b_in   = (const float*)d_in[i]; break;
            case 16777216: W_main = (const float*)d_in[i]; break;
            case 8192:     b_main = (const float*)d_in[i]; break;
            case 65536:    b_g2   = (const float*)d_in[i]; break;
            case 131072:   W_out  = (const float*)d_in[i]; break;
            case 64:       b_out  = (const float*)d_in[i]; break;
            case 8388608:  if (n8 < 2) w8[n8++] = (const float*)d_in[i]; break;
            case 4096:     if (n4 < 2) c4[n4++] = d_in[i]; break;
            default: break;
        }
    }
    const float* W_g1 = w8[0];
    const float* W_g2 = w8[1];
    float* out = (float*)d_out;

    __half* x_ptr;   cudaGetSymbolAddress((void**)&x_ptr, g_x);
    float*  y_ptr;   cudaGetSymbolAddress((void**)&y_ptr, g_y);
    __half* sr_ptr;  cudaGetSymbolAddress((void**)&sr_ptr, g_sr);
    __half* wmt_ptr; cudaGetSymbolAddress((void**)&wmt_ptr, g_Wmt);
    __half* wg1t_ptr;cudaGetSymbolAddress((void**)&wg1t_ptr, g_Wg1t);
    __half* wg2t_ptr;cudaGetSymbolAddress((void**)&wg2t_ptr, g_Wg2t);
    __half* wint_ptr;cudaGetSymbolAddress((void**)&wint_ptr, g_Wint);
    __half* wot_ptr; cudaGetSymbolAddress((void**)&wot_ptr, g_Wot);

    const int smem_dense = 4 * H_STG * 2;              // 81920
    const int smem_g2    = 4 * H_STG * 2 + 128 * 4;    // 82432
    const int smem_g1    = 4 * G1_STG_H * 2 + 32 * 4;  // 51328
    const int smem_out   = 4 * OUT_STG_H * 2;          // 61440
    cudaFuncSetAttribute(hgemm,     cudaFuncAttributeMaxDynamicSharedMemorySize, smem_dense);
    cudaFuncSetAttribute(hgemm_g2,  cudaFuncAttributeMaxDynamicSharedMemorySize, smem_g2);
    cudaFuncSetAttribute(hgemm_g1p, cudaFuncAttributeMaxDynamicSharedMemorySize, smem_g1);
    cudaFuncSetAttribute(hgemm_out, cudaFuncAttributeMaxDynamicSharedMemorySize, smem_out);

    dim3 blk(256);
    dim3 tblk(32, 8);

    build_routing<<<1, 256>>>((const int*)c4[0], (const int*)c4[1]);

    round_s<<<BB * SS / 1024, 256>>>(s);
    // transpose: grid (N/32, K/64, batch)
    transpose_h<<<dim3(HH / 32, SS / 64, 1), tblk>>>(W_in, wint_ptr, SS, HH);
    transpose_h<<<dim3(HH / 32, HH / 64, LL), tblk>>>(W_main, wmt_ptr, HH, HH);
    transpose_h<<<dim3(RR / 32, HH / 64, LL * GG), tblk>>>(W_g1, wg1t_ptr, HH, RR);
    transpose_h<<<dim3(HH / 32, RR / 64, LL * GG), tblk>>>(W_g2, wg2t_ptr, RR, HH);
    transpose_h<<<dim3(AA / 32, HH / 64, 1), tblk>>>(W_out, wot_ptr, HH, AA);

    // x = fp16(s @ W_in + b_in)   (col-pair: grid.x = HH/256)
    hgemm<<<dim3(HH / 256, BB / 128), blk, smem_dense>>>(
        sr_ptr, SS, wint_ptr, SS, b_in, nullptr, x_ptr, HH, SS);

    for (int l = 0; l < LL; l++) {
        // y = x @ W_main[l] + b_main[l]  (fp32 out, col-pair)
        hgemm<<<dim3(HH / 256, BB / 128), blk, smem_dense>>>(
            x_ptr, HH, wmt_ptr + (size_t)l * HH * HH, HH,
            b_main + (size_t)l * HH, y_ptr, nullptr, HH, HH);
        hgemm_g1p<<<dim3(4, BB / 32, GG), blk, smem_g1>>>(l);
        reduce_h1<<<BB * RR / 1024, 256>>>(l);
        hgemm_g2<<<dim3(HH / 256, BB / 128, GG), blk, smem_g2>>>(b_g2, l);
    }

    // out = x @ W_out + b_out  (fp16 MMA split-K 8 + reduce)
    hgemm_out<<<dim3(1, BB / 128, 8), blk, smem_out>>>(x_ptr, wot_ptr);
    reduce_out<<<BB * AA / 256, 256>>>(b_out, out);
}

// round 17
// speedup vs baseline: 1.0643x; 1.0643x over previous
#include <cuda_runtime.h>
#include <cuda_fp16.h>
#include <math.h>
#include <stdint.h>

// Problem constants  (L,G,H,R,S,A,B = 4,8,2048,128,512,64,4096)
#define BB 4096
#define SS 512
#define HH 2048
#define RR 128
#define AA 64
#define GG 8
#define LL 4

// ---------------------------------------------------------------------------
// Scratch (device globals)
// ---------------------------------------------------------------------------
__device__ __align__(16) __half g_x[(size_t)BB * HH];     // activations (fp16)
__device__ __align__(16) __half g_y[(size_t)BB * HH];     // main branch (fp16)
__device__ __align__(16) __half g_h1[(size_t)BB * RR];    // low-rank mid (fp16)
__device__ __align__(16) float  g_h1p[4][(size_t)BB * RR];
__device__ __align__(16) float  g_outp[8][(size_t)BB * AA];
__device__ __align__(16) __half g_Wmt[(size_t)LL * HH * HH];       // W_main^T
__device__ __align__(16) __half g_Wg1t[(size_t)LL * GG * HH * RR]; // W_g1^T
__device__ __align__(16) __half g_Wg2t[(size_t)LL * GG * RR * HH]; // W_g2^T
__device__ __align__(16) __half g_Wint[(size_t)SS * HH];           // W_in^T
__device__ __align__(16) __half g_Wot[(size_t)AA * HH];            // W_out^T
__device__ __align__(16) __half g_sr[(size_t)BB * SS];             // s fp16
__device__ int g_cnt[GG];
__device__ int g_rows[GG * BB];
__device__ int g_eid[BB];
__device__ const float* g_bg1_ptr;

// ---------------------------------------------------------------------------
// helpers
// ---------------------------------------------------------------------------
__device__ __forceinline__ void mma_f16(float* d, const uint32_t* a,
                                        const uint32_t* b) {
    asm volatile(
        "mma.sync.aligned.m16n8k16.row.col.f32.f16.f16.f32 "
        "{%0,%1,%2,%3}, {%4,%5,%6,%7}, {%8,%9}, {%0,%1,%2,%3};"
        : "+f"(d[0]), "+f"(d[1]), "+f"(d[2]), "+f"(d[3])
        : "r"(a[0]), "r"(a[1]), "r"(a[2]), "r"(a[3]), "r"(b[0]), "r"(b[1]));
}
__device__ __forceinline__ void ldsm4(uint32_t& r0, uint32_t& r1, uint32_t& r2,
                                      uint32_t& r3, uint32_t addr) {
    asm volatile("ldmatrix.sync.aligned.m8n8.x4.shared.b16 {%0,%1,%2,%3}, [%4];"
                 : "=r"(r0), "=r"(r1), "=r"(r2), "=r"(r3) : "r"(addr));
}
__device__ __forceinline__ float elu1(float v) {
    return v > 0.0f ? v : expm1f(v);
}
__device__ __forceinline__ void cp16(uint32_t s, const void* g) {
    asm volatile("cp.async.ca.shared.global [%0], [%1], 16;" :: "r"(s), "l"(g));
}
#define CP_COMMIT() asm volatile("cp.async.commit_group;")
#define CP_WAITG(n) asm volatile("cp.async.wait_group %0;" :: "n"(n))

#define HSTR 40                  // halves per smem row (32 data + 8 pad = 80B)
#define H_TILE (128 * HSTR)      // halves per 128-row tile
#define H_STG  (2 * H_TILE)      // halves per stage (A+B), 20480 B
#define G1_A_H (32 * HSTR)       // halves per 32-row A tile
#define G1_STG_H (G1_A_H + H_TILE)  // 6400 halves = 12800 B
#define OUT_B_H (64 * HSTR)      // 64-row B tile (out GEMM)
#define OUT_STG_H (H_TILE + OUT_B_H)  // 7680 halves = 15360 B

// ---------------------------------------------------------------------------
// Routing (resolves {o, b_g1} size-4096 ambiguity by content)
// ---------------------------------------------------------------------------
__global__ void build_routing(const int* __restrict__ c0,
                              const int* __restrict__ c1)
{
    __shared__ const int* o_ptr;
    __shared__ int stride;
    int tid = threadIdx.x;
    if (tid == 0) {
        const int* cands[2] = {c0, c1};
        int pick = 0; stride = 1;
        for (int c = 0; c < 2; c++) {
            const int* p = cands[c];
            bool ok32 = true, nz32 = false;
            for (int i = 0; i < 256; i++) {
                int v = p[i];
                if (v < 0 || v >= GG) { ok32 = false; break; }
                if (v) nz32 = true;
            }
            if (ok32 && nz32) { pick = c; stride = 1; break; }
            bool ok64 = true, nz64 = false;
            for (int i = 0; i < 256; i++) {
                int lo = p[2 * i], hi = p[2 * i + 1];
                if (hi != 0 || lo < 0 || lo >= GG) { ok64 = false; break; }
                if (lo) nz64 = true;
            }
            if (ok64 && nz64) { pick = c; stride = 2; break; }
        }
        o_ptr = cands[pick];
        g_bg1_ptr = (const float*)cands[1 - pick];
    }
    if (tid < GG) g_cnt[tid] = 0;
    __syncthreads();
    const int* o = o_ptr;
    const int st = stride;
    for (int b = tid; b < BB; b += blockDim.x) {
        int e = o[(size_t)b * st];
        g_eid[b] = e;
        int idx = atomicAdd(&g_cnt[e], 1);
        g_rows[e * BB + idx] = b;
    }
}

// ---------------------------------------------------------------------------
// Prep: transpose + fp16 convert. src [K][N] fp32 (batched) -> dst [N][K] fp16.
// Tile 64(K) x 32(N). K mult of 64, N mult of 32.
// ---------------------------------------------------------------------------
__global__ void transpose_h(const float* __restrict__ src,
                            __half* __restrict__ dst, int K, int N)
{
    __shared__ float t[64][33];
    const size_t mb = (size_t)blockIdx.z * K * N;
    int k0 = blockIdx.y * 64, n0 = blockIdx.x * 32;
    int x = threadIdx.x, y = threadIdx.y;  // 32x8
#pragma unroll
    for (int i = y; i < 64; i += 8)
        t[i][x] = src[mb + (size_t)(k0 + i) * N + n0 + x];
    __syncthreads();
#pragma unroll
    for (int j = y; j < 32; j += 8) {
        __half2 v = __floats2half2_rn(t[2 * x][j], t[2 * x + 1][j]);
        *(__half2*)(dst + mb + (size_t)(n0 + j) * K + k0 + 2 * x) = v;
    }
}

__global__ void round_s(const float* __restrict__ s)
{
    int idx = (blockIdx.x * 256 + threadIdx.x) * 4;
    float4 v = *(const float4*)(s + idx);
    *(__half2*)(g_sr + idx)     = __floats2half2_rn(v.x, v.y);
    *(__half2*)(g_sr + idx + 2) = __floats2half2_rn(v.z, v.w);
}

// ---------------------------------------------------------------------------
// Dense fp16 GEMM (m16n8k16), 4-stage cp.async ring, single sync per tile.
// CTA 128x128, 256 threads = 8 warps, each 64x32.  BK=32.  fp16 out.
// K mult of 128.
// ---------------------------------------------------------------------------
__global__ __launch_bounds__(256)
void hgemm(const __half* __restrict__ A, int lda,
           const __half* __restrict__ Bt, int ldb,
           const float* __restrict__ bias, __half* Ch,
           int N, int K)
{
    extern __shared__ __half hsm[];
    const int tid = threadIdx.x, lane = tid & 31, wid = tid >> 5;
    const int wm = (wid & 1) * 64, wn = (wid >> 1) * 32;
    const int row0 = blockIdx.y * 128, col0 = blockIdx.x * 128;
    const int r = lane >> 2, cq = lane & 3;
    const uint32_t sbase = (uint32_t)__cvta_generic_to_shared(hsm);

    const uint32_t aAddr0 = sbase +
        ((wm + (lane & 15)) * HSTR + ((lane >> 4) << 3)) * 2;
    const uint32_t bAddr0 = sbase + H_TILE * 2 +
        ((wn + ((lane >> 4) << 3) + (lane & 7)) * HSTR +
         (((lane >> 3) & 1) << 3)) * 2;

    float acc[4][4][4];
#pragma unroll
    for (int t = 0; t < 4; t++)
#pragma unroll
        for (int u = 0; u < 4; u++)
#pragma unroll
            for (int v = 0; v < 4; v++) acc[t][u][v] = 0.0f;

    const int NT = K >> 5;
    auto load_tile = [&](int slot, int k0) {
        const uint32_t sA = sbase + slot * H_STG * 2;
        const uint32_t sB = sA + H_TILE * 2;
#pragma unroll
        for (int i = 0; i < 2; i++) {
            int cc = tid + i * 256;
            int m = cc >> 2, c = cc & 3;
            cp16(sA + (m * HSTR + c * 8) * 2,
                 A + (size_t)(row0 + m) * lda + k0 + c * 8);
            cp16(sB + (m * HSTR + c * 8) * 2,
                 Bt + (size_t)(col0 + m) * ldb + k0 + c * 8);
        }
    };

    load_tile(0, 0);  CP_COMMIT();
    load_tile(1, 32); CP_COMMIT();
    load_tile(2, 64); CP_COMMIT();

    for (int kt = 0; kt < NT; kt++) {
        CP_WAITG(2);
        __syncthreads();
        if (kt + 3 < NT) load_tile((kt + 3) & 3, (kt + 3) * 32);
        CP_COMMIT();
        const uint32_t off = (kt & 3) * H_STG * 2;
#pragma unroll
        for (int ks = 0; ks < 2; ks++) {
            const uint32_t kb = ks * 32;   // 16 halves = 32 bytes
            uint32_t af[4][4], bf[4][2];
#pragma unroll
            for (int t = 0; t < 4; t++)
                ldsm4(af[t][0], af[t][1], af[t][2], af[t][3],
                      aAddr0 + off + t * 16 * HSTR * 2 + kb);
#pragma unroll
            for (int j = 0; j < 2; j++)
                ldsm4(bf[2*j][0], bf[2*j][1], bf[2*j+1][0], bf[2*j+1][1],
                      bAddr0 + off + j * 16 * HSTR * 2 + kb);
#pragma unroll
            for (int t = 0; t < 4; t++)
#pragma unroll
                for (int u = 0; u < 4; u++)
                    mma_f16(acc[t][u], af[t], bf[u]);
        }
    }

#pragma unroll
    for (int t = 0; t < 4; t++) {
        int row_a = row0 + wm + t * 16 + r;
#pragma unroll
        for (int u = 0; u < 4; u++) {
            int col = col0 + wn + u * 8 + cq * 2;
            float b0 = bias[col], b1 = bias[col + 1];
            *(__half2*)(Ch + (size_t)row_a * N + col) =
                __floats2half2_rn(acc[t][u][0] + b0, acc[t][u][1] + b1);
            *(__half2*)(Ch + (size_t)(row_a + 8) * N + col) =
                __floats2half2_rn(acc[t][u][2] + b0, acc[t][u][3] + b1);
        }
    }
}

// ---------------------------------------------------------------------------
// g1 split-K partial (fp16, 4-stage, single sync): BM=32, N=RR, K chunk 512.
// 4 splits.  256 threads, 8 warps each 32x16.
// ---------------------------------------------------------------------------
__global__ __launch_bounds__(256)
void hgemm_g1p(int l)
{
    const int g = blockIdx.z;
    const int cnt = g_cnt[g];
    const int mbase = blockIdx.y * 32;
    if (mbase >= cnt) return;
    const int split = blockIdx.x;
    const int kstart = split * (HH / 4);
    const int* rows = g_rows + g * BB;
    const __half* Bt = g_Wg1t + ((size_t)(l * GG + g)) * HH * RR;  // [RR][HH]
    float* outp = g_h1p[split];

    extern __shared__ __half hsm[];
    int* rows_s = (int*)(hsm + 4 * G1_STG_H);
    const uint32_t sbase = (uint32_t)__cvta_generic_to_shared(hsm);

    const int tid = threadIdx.x, lane = tid & 31, wid = tid >> 5;
    const int wn = wid * 16;
    const int r = lane >> 2, cq = lane & 3;

    if (tid < 32) {
        int lr = mbase + tid;
        rows_s[tid] = rows[lr < cnt ? lr : (cnt - 1)];
    }
    __syncthreads();

    const uint32_t aAddr0 = sbase +
        ((lane & 15) * HSTR + ((lane >> 4) << 3)) * 2;
    const uint32_t bAddr0 = sbase + G1_A_H * 2 +
        ((wn + ((lane >> 4) << 3) + (lane & 7)) * HSTR +
         (((lane >> 3) & 1) << 3)) * 2;

    float acc[2][2][4];
#pragma unroll
    for (int t = 0; t < 2; t++)
#pragma unroll
        for (int u = 0; u < 2; u++)
#pragma unroll
            for (int v = 0; v < 4; v++) acc[t][u][v] = 0.0f;

    const int NT = 16;   // 512/32
    auto load_tile = [&](int slot, int k0) {
        const uint32_t sA = sbase + slot * G1_STG_H * 2;
        const uint32_t sB = sA + G1_A_H * 2;
        if (tid < 128) {   // A: 32 rows x 4 chunks
            int m = tid >> 2, c = tid & 3;
            cp16(sA + (m * HSTR + c * 8) * 2,
                 g_x + (size_t)rows_s[m] * HH + k0 + c * 8);
        }
#pragma unroll
        for (int i = 0; i < 2; i++) {  // B: 128 rows x 4 chunks
            int cc = tid + i * 256;
            int m = cc >> 2, c = cc & 3;
            cp16(sB + (m * HSTR + c * 8) * 2,
                 Bt + (size_t)m * HH + k0 + c * 8);
        }
    };

#pragma unroll
    for (int p = 0; p < 3; p++) { load_tile(p, kstart + p * 32); CP_COMMIT(); }

    for (int kt = 0; kt < NT; kt++) {
        CP_WAITG(2);
        __syncthreads();
        if (kt + 3 < NT) load_tile((kt + 3) & 3, kstart + (kt + 3) * 32);
        CP_COMMIT();
        const uint32_t off = (kt & 3) * G1_STG_H * 2;
#pragma unroll
        for (int ks = 0; ks < 2; ks++) {
            const uint32_t kb = ks * 32;
            uint32_t af[2][4], bf[2][2];
#pragma unroll
            for (int t = 0; t < 2; t++)
                ldsm4(af[t][0], af[t][1], af[t][2], af[t][3],
                      aAddr0 + off + t * 16 * HSTR * 2 + kb);
            ldsm4(bf[0][0], bf[0][1], bf[1][0], bf[1][1], bAddr0 + off + kb);
#pragma unroll
            for (int t = 0; t < 2; t++)
#pragma unroll
                for (int u = 0; u < 2; u++)
                    mma_f16(acc[t][u], af[t], bf[u]);
        }
    }

#pragma unroll
    for (int t = 0; t < 2; t++) {
        int lr0 = mbase + t * 16 + r;
#pragma unroll
        for (int u = 0; u < 2; u++) {
            int col = wn + u * 8 + cq * 2;
            if (lr0 < cnt) {
                int row = rows[lr0];
                *(float2*)(outp + (size_t)row * RR + col) =
                    {acc[t][u][0], acc[t][u][1]};
            }
            if (lr0 + 8 < cnt) {
                int row = rows[lr0 + 8];
                *(float2*)(outp + (size_t)row * RR + col) =
                    {acc[t][u][2], acc[t][u][3]};
            }
        }
    }
}

// h1 = fp16(sum of 4 partials + b_g1[l, eid]), vectorized x4
__global__ void reduce_h1(int l)
{
    int idx = (blockIdx.x * 256 + threadIdx.x) * 4;
    int b = idx >> 7, c = idx & 127;
    float4 v0 = *(const float4*)(g_h1p[0] + idx);
    float4 v1 = *(const float4*)(g_h1p[1] + idx);
    float4 v2 = *(const float4*)(g_h1p[2] + idx);
    float4 v3 = *(const float4*)(g_h1p[3] + idx);
    const float* bp = g_bg1_ptr + (l * GG + g_eid[b]) * RR + c;
    float r0 = v0.x + v1.x + v2.x + v3.x + bp[0];
    float r1 = v0.y + v1.y + v2.y + v3.y + bp[1];
    float r2 = v0.z + v1.z + v2.z + v3.z + bp[2];
    float r3 = v0.w + v1.w + v2.w + v3.w + bp[3];
    *(__half2*)(g_h1 + idx)     = __floats2half2_rn(r0, r1);
    *(__half2*)(g_h1 + idx + 2) = __floats2half2_rn(r2, r3);
}

// ---------------------------------------------------------------------------
// g2 + fused ELU (fp16): BM=128, BN=128, K=RR=128, 3-stage, single sync.
// 256 threads, 8 warps each 64x32.
// x_next = fp16(elu(y + h1 @ Wg2t[l,g]^T + b_g2[l,g]))  (y now fp16)
// ---------------------------------------------------------------------------
__global__ __launch_bounds__(256)
void hgemm_g2(const float* __restrict__ bg2, int l)
{
    const int g = blockIdx.z;
    const int cnt = g_cnt[g];
    const int mbase = blockIdx.y * 128;
    if (mbase >= cnt) return;
    const int* rows = g_rows + g * BB;
    const int col0 = blockIdx.x * 128;
    const __half* Bt  = g_Wg2t + ((size_t)(l * GG + g)) * RR * HH;  // [HH][RR]
    const float* bias = bg2 + (size_t)(l * GG + g) * HH;

    extern __shared__ __half hsm[];
    int* rows_s = (int*)(hsm + 3 * H_STG);
    const uint32_t sbase = (uint32_t)__cvta_generic_to_shared(hsm);

    const int tid = threadIdx.x, lane = tid & 31, wid = tid >> 5;
    const int wm = (wid & 1) * 64, wn = (wid >> 1) * 32;
    const int r = lane >> 2, cq = lane & 3;

    if (tid < 128) {
        int lr = mbase + tid;
        rows_s[tid] = rows[lr < cnt ? lr : (cnt - 1)];
    }
    __syncthreads();

    const uint32_t aAddr0 = sbase +
        ((wm + (lane & 15)) * HSTR + ((lane >> 4) << 3)) * 2;
    const uint32_t bAddr0 = sbase + H_TILE * 2 +
        ((wn + ((lane >> 4) << 3) + (lane & 7)) * HSTR +
         (((lane >> 3) & 1) << 3)) * 2;

    float acc[4][4][4];
#pragma unroll
    for (int t = 0; t < 4; t++)
#pragma unroll
        for (int u = 0; u < 4; u++)
#pragma unroll
            for (int v = 0; v < 4; v++) acc[t][u][v] = 0.0f;

    const int NT = RR >> 5;  // 4
    auto load_tile = [&](int slot, int k0) {
        const uint32_t sA = sbase + slot * H_STG * 2;
        const uint32_t sB = sA + H_TILE * 2;
#pragma unroll
        for (int i = 0; i < 2; i++) {
            int cc = tid + i * 256;
            int m = cc >> 2, c = cc & 3;
            cp16(sA + (m * HSTR + c * 8) * 2,
                 g_h1 + (size_t)rows_s[m] * RR + k0 + c * 8);
            cp16(sB + (m * HSTR + c * 8) * 2,
                 Bt + (size_t)(col0 + m) * RR + k0 + c * 8);
        }
    };

    load_tile(0, 0);  CP_COMMIT();
    load_tile(1, 32); CP_COMMIT();

    for (int kt = 0; kt < NT; kt++) {
        CP_WAITG(1);
        __syncthreads();
        if (kt + 2 < NT) load_tile((kt + 2) % 3, (kt + 2) * 32);
        CP_COMMIT();
        const uint32_t off = (kt % 3) * H_STG * 2;
#pragma unroll
        for (int ks = 0; ks < 2; ks++) {
            const uint32_t kb = ks * 32;
            uint32_t af[4][4], bf[4][2];
#pragma unroll
            for (int t = 0; t < 4; t++)
                ldsm4(af[t][0], af[t][1], af[t][2], af[t][3],
                      aAddr0 + off + t * 16 * HSTR * 2 + kb);
#pragma unroll
            for (int j = 0; j < 2; j++)
                ldsm4(bf[2*j][0], bf[2*j][1], bf[2*j+1][0], bf[2*j+1][1],
                      bAddr0 + off + j * 16 * HSTR * 2 + kb);
#pragma unroll
            for (int t = 0; t < 4; t++)
#pragma unroll
                for (int u = 0; u < 4; u++)
                    mma_f16(acc[t][u], af[t], bf[u]);
        }
    }

#pragma unroll
    for (int t = 0; t < 4; t++) {
        int lr0 = mbase + wm + t * 16 + r;
#pragma unroll
        for (int u = 0; u < 4; u++) {
            int col = col0 + wn + u * 8 + cq * 2;
            float b0 = bias[col], b1 = bias[col + 1];
            if (lr0 < cnt) {
                int row = rows[lr0];
                __half2 yv = *(const __half2*)(g_y + (size_t)row * HH + col);
                *(__half2*)(g_x + (size_t)row * HH + col) =
                    __floats2half2_rn(
                        elu1(__half2float(yv.x) + acc[t][u][0] + b0),
                        elu1(__half2float(yv.y) + acc[t][u][1] + b1));
            }
            if (lr0 + 8 < cnt) {
                int row = rows[lr0 + 8];
                __half2 yv = *(const __half2*)(g_y + (size_t)row * HH + col);
                *(__half2*)(g_x + (size_t)row * HH + col) =
                    __floats2half2_rn(
                        elu1(__half2float(yv.x) + acc[t][u][2] + b0),
                        elu1(__half2float(yv.y) + acc[t][u][3] + b1));
            }
        }
    }
}

// ---------------------------------------------------------------------------
// Output GEMM (fp16 MMA, split-K 8): partial[M,64] = x[M,kc] @ Wot[64,kc]^T
// BM=128, BN=64, BK=32, K chunk 256 (NT=8).  8 warps each 64x16.  4-stage.
// ---------------------------------------------------------------------------
__global__ __launch_bounds__(256)
void hgemm_out(const __half* __restrict__ A, const __half* __restrict__ Bt)
{
    extern __shared__ __half hsm[];
    const int tid = threadIdx.x, lane = tid & 31, wid = tid >> 5;
    const int wm = (wid & 1) * 64, wn = (wid >> 1) * 16;
    const int row0 = blockIdx.y * 128;
    const int split = blockIdx.z;
    const int kstart = split * 256;
    float* outp = g_outp[split];
    const int r = lane >> 2, cq = lane & 3;
    const uint32_t sbase = (uint32_t)__cvta_generic_to_shared(hsm);

    const uint32_t aAddr0 = sbase +
        ((wm + (lane & 15)) * HSTR + ((lane >> 4) << 3)) * 2;
    const uint32_t bAddr0 = sbase + H_TILE * 2 +
        ((wn + ((lane >> 4) << 3) + (lane & 7)) * HSTR +
         (((lane >> 3) & 1) << 3)) * 2;

    float acc[4][2][4];
#pragma unroll
    for (int t = 0; t < 4; t++)
#pragma unroll
        for (int u = 0; u < 2; u++)
#pragma unroll
            for (int v = 0; v < 4; v++) acc[t][u][v] = 0.0f;

    const int NT = 8;  // 256/32
    auto load_tile = [&](int slot, int k0) {
        const uint32_t sA = sbase + slot * OUT_STG_H * 2;
        const uint32_t sB = sA + H_TILE * 2;
#pragma unroll
        for (int i = 0; i < 2; i++) {   // A: 128 rows x 4 chunks = 512
            int cc = tid + i * 256;
            int m = cc >> 2, c = cc & 3;
            cp16(sA + (m * HSTR + c * 8) * 2,
                 A + (size_t)(row0 + m) * HH + k0 + c * 8);
        }
        {   // B: 64 rows x 4 chunks = 256
            int m = tid >> 2, c = tid & 3;
            if (m < 64)
                cp16(sB + (m * HSTR + c * 8) * 2,
                     Bt + (size_t)m * HH + k0 + c * 8);
        }
    };

#pragma unroll
    for (int p = 0; p < 3; p++) { load_tile(p, kstart + p * 32); CP_COMMIT(); }

    for (int kt = 0; kt < NT; kt++) {
        CP_WAITG(2);
        __syncthreads();
        if (kt + 3 < NT) load_tile((kt + 3) & 3, kstart + (kt + 3) * 32);
        CP_COMMIT();
        const uint32_t off = (kt & 3) * OUT_STG_H * 2;
#pragma unroll
        for (int ks = 0; ks < 2; ks++) {
            const uint32_t kb = ks * 32;
            uint32_t af[4][4], bf[2][2];
#pragma unroll
            for (int t = 0; t < 4; t++)
                ldsm4(af[t][0], af[t][1], af[t][2], af[t][3],
                      aAddr0 + off + t * 16 * HSTR * 2 + kb);
            ldsm4(bf[0][0], bf[0][1], bf[1][0], bf[1][1], bAddr0 + off + kb);
#pragma unroll
            for (int t = 0; t < 4; t++)
#pragma unroll
                for (int u = 0; u < 2; u++)
                    mma_f16(acc[t][u], af[t], bf[u]);
        }
    }

#pragma unroll
    for (int t = 0; t < 4; t++) {
        int row_a = row0 + wm + t * 16 + r;
#pragma unroll
        for (int u = 0; u < 2; u++) {
            int col = wn + u * 8 + cq * 2;
            *(float2*)(outp + (size_t)row_a * AA + col) =
                {acc[t][u][0], acc[t][u][1]};
            *(float2*)(outp + (size_t)(row_a + 8) * AA + col) =
                {acc[t][u][2], acc[t][u][3]};
        }
    }
}

__global__ void reduce_out(const float* __restrict__ bout,
                           float* __restrict__ out)
{
    int idx = blockIdx.x * 256 + threadIdx.x;
    float v = 0.0f;
#pragma unroll
    for (int p = 0; p < 8; p++) v += g_outp[p][idx];
    out[idx] = v + bout[idx & (AA - 1)];
}

// ---------------------------------------------------------------------------
// Launch
// ---------------------------------------------------------------------------
extern "C" void kernel_launch(void* const* d_in, const int* in_sizes, int n_in,
                              void* d_out, int out_size)
{
    const float* s = 0; const float* W_in = 0; const float* b_in = 0;
    const float* W_main = 0; const float* b_main = 0; const float* b_g2 = 0;
    const float* W_out = 0; const float* b_out = 0;
    const float* w8[2] = {0, 0};
    const void*  c4[2] = {0, 0};
    int n8 = 0, n4 = 0;

    for (int i = 0; i < n_in; i++) {
        switch (in_sizes[i]) {
            case 2097152:  s      = (const float*)d_in[i]; break;
            case 1048576:  W_in   = (const float*)d_in[i]; break;
            case 2048:     b_in   = (const float*)d_in[i]; break;
            case 16777216: W_main = (const float*)d_in[i]; break;
            case 8192:     b_main = (const float*)d_in[i]; break;
            case 65536:    b_g2   = (const float*)d_in[i]; break;
            case 131072:   W_out  = (const float*)d_in[i]; break;
            case 64:       b_out  = (const float*)d_in[i]; break;
            case 8388608:  if (n8 < 2) w8[n8++] = (const float*)d_in[i]; break;
            case 4096:     if (n4 < 2) c4[n4++] = d_in[i]; break;
            default: break;
        }
    }
    const float* W_g1 = w8[0];
    const float* W_g2 = w8[1];
    float* out = (float*)d_out;

    __half* x_ptr;   cudaGetSymbolAddress((void**)&x_ptr, g_x);
    __half* y_ptr;   cudaGetSymbolAddress((void**)&y_ptr, g_y);
    __half* sr_ptr;  cudaGetSymbolAddress((void**)&sr_ptr, g_sr);
    __half* wmt_ptr; cudaGetSymbolAddress((void**)&wmt_ptr, g_Wmt);
    __half* wg1t_ptr;cudaGetSymbolAddress((void**)&wg1t_ptr, g_Wg1t);
    __half* wg2t_ptr;cudaGetSymbolAddress((void**)&wg2t_ptr, g_Wg2t);
    __half* wint_ptr;cudaGetSymbolAddress((void**)&wint_ptr, g_Wint);
    __half* wot_ptr; cudaGetSymbolAddress((void**)&wot_ptr, g_Wot);

    const int smem_dense = 4 * H_STG * 2;              // 81920
    const int smem_g2    = 3 * H_STG * 2 + 128 * 4;    // 61952
    const int smem_g1    = 4 * G1_STG_H * 2 + 32 * 4;  // 51328
    const int smem_out   = 4 * OUT_STG_H * 2;          // 61440
    cudaFuncSetAttribute(hgemm,     cudaFuncAttributeMaxDynamicSharedMemorySize, smem_dense);
    cudaFuncSetAttribute(hgemm_g2,  cudaFuncAttributeMaxDynamicSharedMemorySize, smem_g2);
    cudaFuncSetAttribute(hgemm_g1p, cudaFuncAttributeMaxDynamicSharedMemorySize, smem_g1);
    cudaFuncSetAttribute(hgemm_out, cudaFuncAttributeMaxDynamicSharedMemorySize, smem_out);

    dim3 blk(256);
    dim3 tblk(32, 8);

    build_routing<<<1, 256>>>((const int*)c4[0], (const int*)c4[1]);

    round_s<<<BB * SS / 1024, 256>>>(s);
    // transpose: grid (N/32, K/64, batch)
    transpose_h<<<dim3(HH / 32, SS / 64, 1), tblk>>>(W_in, wint_ptr, SS, HH);
    transpose_h<<<dim3(HH / 32, HH / 64, LL), tblk>>>(W_main, wmt_ptr, HH, HH);
    transpose_h<<<dim3(RR / 32, HH / 64, LL * GG), tblk>>>(W_g1, wg1t_ptr, HH, RR);
    transpose_h<<<dim3(HH / 32, RR / 64, LL * GG), tblk>>>(W_g2, wg2t_ptr, RR, HH);
    transpose_h<<<dim3(AA / 32, HH / 64, 1), tblk>>>(W_out, wot_ptr, HH, AA);

    // x = fp16(s @ W_in + b_in)
    hgemm<<<dim3(HH / 128, BB / 128), blk, smem_dense>>>(
        sr_ptr, SS, wint_ptr, SS, b_in, x_ptr, HH, SS);

    for (int l = 0; l < LL; l++) {
        // y = fp16(x @ W_main[l] + b_main[l])
        hgemm<<<dim3(HH / 128, BB / 128), blk, smem_dense>>>(
            x_ptr, HH, wmt_ptr + (size_t)l * HH * HH, HH,
            b_main + (size_t)l * HH, y_ptr, HH, HH);
        hgemm_g1p<<<dim3(4, BB / 32, GG), blk, smem_g1>>>(l);
        reduce_h1<<<BB * RR / 1024, 256>>>(l);
        hgemm_g2<<<dim3(HH / 128, BB / 128, GG), blk, smem_g2>>>(b_g2, l);
    }

    // out = x @ W_out + b_out  (fp16 MMA split-K 8 + reduce)
    hgemm_out<<<dim3(1, BB / 128, 8), blk, smem_out>>>(x_ptr, wot_ptr);
    reduce_out<<<BB * AA / 256, 256>>>(b_out, out);
}